// round 1
// baseline (speedup 1.0000x reference)
#include <cuda_runtime.h>
#include <math.h>

#define EMBED 1024
#define NH 16
#define DK 64
#define BATCH 2
#define SEQ 2048
#define M_ROWS (BATCH*SEQ)      // 4096
#define QKV_COLS (3*EMBED)      // 3072

// Scratch (allocation-free rule: __device__ globals)
__device__ float g_q[BATCH*NH*SEQ*DK];       // [B,H,N,dk]
__device__ float g_k[BATCH*NH*SEQ*DK];
__device__ float g_v[BATCH*NH*SEQ*DK];
__device__ float g_attn[M_ROWS*EMBED];       // [B,N,C]

// ---------------------------------------------------------------------------
// Tiled SGEMM (NT): C[m,n] = dot(A[m,:], W[n,:]) + bias[n]
// 128x128 tile, BK=8, 256 threads, 8x8 per thread.
// ---------------------------------------------------------------------------

// QKV GEMM: A = x [4096,1024], W = w_qkv [3072,1024].
// Epilogue scatters into g_q/g_k/g_v in [B,H,N,dk] layout.
__global__ void __launch_bounds__(256) sgemm_qkv(const float* __restrict__ A,
                                                 const float* __restrict__ W,
                                                 const float* __restrict__ bias)
{
    const int K = 1024;
    const int bm = blockIdx.y * 128;
    const int bn = blockIdx.x * 128;

    __shared__ float As[8][128];
    __shared__ float Bs[8][128];

    const int tid = threadIdx.x;
    const int lr = tid >> 1;          // 0..127
    const int lc = (tid & 1) * 4;     // 0 or 4
    const int ty = tid >> 4;          // 0..15
    const int tx = tid & 15;          // 0..15

    const float* Aptr = A + (size_t)(bm + lr) * K + lc;
    const float* Wptr = W + (size_t)(bn + lr) * K + lc;

    float acc[8][8];
#pragma unroll
    for (int i = 0; i < 8; i++)
#pragma unroll
        for (int j = 0; j < 8; j++) acc[i][j] = 0.f;

    for (int k0 = 0; k0 < K; k0 += 8) {
        float4 a = *(const float4*)(Aptr + k0);
        float4 b = *(const float4*)(Wptr + k0);
        __syncthreads();
        As[lc + 0][lr] = a.x; As[lc + 1][lr] = a.y;
        As[lc + 2][lr] = a.z; As[lc + 3][lr] = a.w;
        Bs[lc + 0][lr] = b.x; Bs[lc + 1][lr] = b.y;
        Bs[lc + 2][lr] = b.z; Bs[lc + 3][lr] = b.w;
        __syncthreads();
#pragma unroll
        for (int k = 0; k < 8; k++) {
            float ar[8], br[8];
#pragma unroll
            for (int i = 0; i < 8; i++) ar[i] = As[k][ty * 8 + i];
#pragma unroll
            for (int j = 0; j < 8; j++) br[j] = Bs[k][tx * 8 + j];
#pragma unroll
            for (int i = 0; i < 8; i++)
#pragma unroll
                for (int j = 0; j < 8; j++)
                    acc[i][j] = fmaf(ar[i], br[j], acc[i][j]);
        }
    }

    // Scatter epilogue: n -> (which, h, d); m -> (b, t)
#pragma unroll
    for (int i = 0; i < 8; i++) {
        const int m = bm + ty * 8 + i;
        const int bi = m >> 11;           // /2048
        const int t  = m & 2047;
#pragma unroll
        for (int j = 0; j < 8; j++) {
            const int n = bn + tx * 8 + j;
            const float v = acc[i][j] + bias[n];
            const int which = n >> 10;    // 0=q,1=k,2=v
            const int cc = n & 1023;
            const int h = cc >> 6;
            const int d = cc & 63;
            float* dst = (which == 0) ? g_q : (which == 1) ? g_k : g_v;
            dst[(((size_t)(bi * NH + h)) * SEQ + t) * DK + d] = v;
        }
    }
}

// Output GEMM: A = g_attn [4096,1024], W = w_o [1024,1024] -> d_out
__global__ void __launch_bounds__(256) sgemm_out(const float* __restrict__ W,
                                                 const float* __restrict__ bias,
                                                 float* __restrict__ C)
{
    const int K = 1024;
    const int bm = blockIdx.y * 128;
    const int bn = blockIdx.x * 128;

    __shared__ float As[8][128];
    __shared__ float Bs[8][128];

    const int tid = threadIdx.x;
    const int lr = tid >> 1;
    const int lc = (tid & 1) * 4;
    const int ty = tid >> 4;
    const int tx = tid & 15;

    const float* Aptr = g_attn + (size_t)(bm + lr) * K + lc;
    const float* Wptr = W + (size_t)(bn + lr) * K + lc;

    float acc[8][8];
#pragma unroll
    for (int i = 0; i < 8; i++)
#pragma unroll
        for (int j = 0; j < 8; j++) acc[i][j] = 0.f;

    for (int k0 = 0; k0 < K; k0 += 8) {
        float4 a = *(const float4*)(Aptr + k0);
        float4 b = *(const float4*)(Wptr + k0);
        __syncthreads();
        As[lc + 0][lr] = a.x; As[lc + 1][lr] = a.y;
        As[lc + 2][lr] = a.z; As[lc + 3][lr] = a.w;
        Bs[lc + 0][lr] = b.x; Bs[lc + 1][lr] = b.y;
        Bs[lc + 2][lr] = b.z; Bs[lc + 3][lr] = b.w;
        __syncthreads();
#pragma unroll
        for (int k = 0; k < 8; k++) {
            float ar[8], br[8];
#pragma unroll
            for (int i = 0; i < 8; i++) ar[i] = As[k][ty * 8 + i];
#pragma unroll
            for (int j = 0; j < 8; j++) br[j] = Bs[k][tx * 8 + j];
#pragma unroll
            for (int i = 0; i < 8; i++)
#pragma unroll
                for (int j = 0; j < 8; j++)
                    acc[i][j] = fmaf(ar[i], br[j], acc[i][j]);
        }
    }

#pragma unroll
    for (int i = 0; i < 8; i++) {
        const int m = bm + ty * 8 + i;
#pragma unroll
        for (int j = 0; j < 8; j++) {
            const int n = bn + tx * 8 + j;
            C[(size_t)m * EMBED + n] = acc[i][j] + bias[n];
        }
    }
}

// ---------------------------------------------------------------------------
// Causal flash attention: one query row per thread, 128 rows per block.
// K/V tiles (64 keys) staged in smem; q, o register-resident.
// Lazy online-softmax rescale (record-max events ~ ln(N) per row).
// ---------------------------------------------------------------------------
__global__ void __launch_bounds__(128) attn_kernel()
{
    const int bh = blockIdx.y;                         // 0..31 (b*16+h)
    const int qrow = blockIdx.x * 128 + threadIdx.x;   // 0..2047

    const float* qptr  = g_q + ((size_t)bh * SEQ + qrow) * DK;
    const float* kbase = g_k + (size_t)bh * SEQ * DK;
    const float* vbase = g_v + (size_t)bh * SEQ * DK;

    __shared__ float Ks[64 * DK];
    __shared__ float Vs[64 * DK];

    float q[DK];
#pragma unroll
    for (int i = 0; i < 16; i++) {
        float4 f = *(const float4*)(qptr + i * 4);
        q[i * 4 + 0] = f.x; q[i * 4 + 1] = f.y;
        q[i * 4 + 2] = f.z; q[i * 4 + 3] = f.w;
    }

    float o[DK];
#pragma unroll
    for (int d = 0; d < DK; d++) o[d] = 0.f;
    float mmax = -INFINITY;
    float l = 0.f;
    const float scale = 0.03125f;  // 1/sqrt(1024)

    const int kend = blockIdx.x * 128 + 127;  // last query row of this block

    for (int k0 = 0; k0 <= kend; k0 += 64) {
        __syncthreads();   // protect previous tile reads
#pragma unroll
        for (int i = 0; i < 8; i++) {
            const int idx = i * 128 + threadIdx.x;   // float4 index 0..1023
            ((float4*)Ks)[idx] = ((const float4*)(kbase + k0 * DK))[idx];
            ((float4*)Vs)[idx] = ((const float4*)(vbase + k0 * DK))[idx];
        }
        __syncthreads();

        int jlim = qrow - k0 + 1;
        if (jlim > 64) jlim = 64;

        for (int j = 0; j < jlim; j++) {
            const float4* kr = (const float4*)(Ks + j * DK);
            float s0 = 0.f, s1 = 0.f, s2 = 0.f, s3 = 0.f;
#pragma unroll
            for (int d4 = 0; d4 < 16; d4++) {
                float4 kv = kr[d4];
                s0 = fmaf(q[d4 * 4 + 0], kv.x, s0);
                s1 = fmaf(q[d4 * 4 + 1], kv.y, s1);
                s2 = fmaf(q[d4 * 4 + 2], kv.z, s2);
                s3 = fmaf(q[d4 * 4 + 3], kv.w, s3);
            }
            float s = ((s0 + s1) + (s2 + s3)) * scale;

            if (s > mmax) {
                const float corr = __expf(mmax - s);   // exp(-inf)=0 first time
                l *= corr;
#pragma unroll
                for (int d = 0; d < DK; d++) o[d] *= corr;
                mmax = s;
            }
            const float p = __expf(s - mmax);
            l += p;

            const float4* vr = (const float4*)(Vs + j * DK);
#pragma unroll
            for (int d4 = 0; d4 < 16; d4++) {
                float4 vv = vr[d4];
                o[d4 * 4 + 0] = fmaf(p, vv.x, o[d4 * 4 + 0]);
                o[d4 * 4 + 1] = fmaf(p, vv.y, o[d4 * 4 + 1]);
                o[d4 * 4 + 2] = fmaf(p, vv.z, o[d4 * 4 + 2]);
                o[d4 * 4 + 3] = fmaf(p, vv.w, o[d4 * 4 + 3]);
            }
        }
    }

    const float inv = 1.0f / l;
    const int bi = bh >> 4;
    const int h = bh & 15;
    float* op = g_attn + ((size_t)(bi * SEQ + qrow)) * EMBED + h * DK;
#pragma unroll
    for (int i = 0; i < 16; i++) {
        float4 f;
        f.x = o[i * 4 + 0] * inv; f.y = o[i * 4 + 1] * inv;
        f.z = o[i * 4 + 2] * inv; f.w = o[i * 4 + 3] * inv;
        *(float4*)(op + i * 4) = f;
    }
}

// ---------------------------------------------------------------------------
extern "C" void kernel_launch(void* const* d_in, const int* in_sizes, int n_in,
                              void* d_out, int out_size)
{
    const float* x     = (const float*)d_in[0];
    const float* w_qkv = (const float*)d_in[1];
    const float* b_qkv = (const float*)d_in[2];
    const float* w_o   = (const float*)d_in[3];
    const float* b_o   = (const float*)d_in[4];
    float* out = (float*)d_out;

    dim3 gqkv(QKV_COLS / 128, M_ROWS / 128);   // (24, 32)
    sgemm_qkv<<<gqkv, 256>>>(x, w_qkv, b_qkv);

    dim3 gattn(SEQ / 128, BATCH * NH);         // (16, 32)
    attn_kernel<<<gattn, 128>>>();

    dim3 gout(EMBED / 128, M_ROWS / 128);      // (8, 32)
    sgemm_out<<<gout, 256>>>(w_o, b_o, out);
}

// round 3
// speedup vs baseline: 1.6976x; 1.6976x over previous
#include <cuda_runtime.h>
#include <cuda_bf16.h>
#include <math.h>
#include <stdint.h>

#define EMBED 1024
#define NH 16
#define DK 64
#define BATCH 2
#define SEQ 2048
#define M_ROWS (BATCH*SEQ)      // 4096
#define QKV_COLS (3*EMBED)      // 3072

// ---------------- scratch (__device__ globals: allocation-free rule) -------
__device__ float g_q[BATCH*NH*SEQ*DK];
__device__ float g_k[BATCH*NH*SEQ*DK];
__device__ float g_v[BATCH*NH*SEQ*DK];
__device__ float g_attn[M_ROWS*EMBED];

__device__ __nv_bfloat16 g_x_hi[M_ROWS*EMBED];
__device__ __nv_bfloat16 g_x_lo[M_ROWS*EMBED];
__device__ __nv_bfloat16 g_wqkv_hi[QKV_COLS*EMBED];
__device__ __nv_bfloat16 g_wqkv_lo[QKV_COLS*EMBED];
__device__ __nv_bfloat16 g_wo_hi[EMBED*EMBED];
__device__ __nv_bfloat16 g_wo_lo[EMBED*EMBED];
__device__ __nv_bfloat16 g_at_hi[M_ROWS*EMBED];
__device__ __nv_bfloat16 g_at_lo[M_ROWS*EMBED];

// ---------------- PTX helpers (plain-target only: sm_80-class) -------------
__device__ __forceinline__ uint32_t smem_u32(const void* p) {
    uint32_t a;
    asm("{ .reg .u64 t; cvta.to.shared.u64 t, %1; cvt.u32.u64 %0, t; }" : "=r"(a) : "l"(p));
    return a;
}
__device__ __forceinline__ void cp16(uint32_t dst, const void* src) {
    asm volatile("cp.async.cg.shared.global [%0], [%1], 16;" :: "r"(dst), "l"(src));
}
#define CP_COMMIT() asm volatile("cp.async.commit_group;" ::: "memory")
#define CP_WAIT0()  asm volatile("cp.async.wait_group 0;" ::: "memory")
#define CP_WAIT1()  asm volatile("cp.async.wait_group 1;" ::: "memory")

__device__ __forceinline__ void ldsm_x4(uint32_t* r, uint32_t addr) {
    asm volatile("ldmatrix.sync.aligned.m8n8.x4.shared.b16 {%0,%1,%2,%3}, [%4];"
                 : "=r"(r[0]), "=r"(r[1]), "=r"(r[2]), "=r"(r[3]) : "r"(addr));
}
__device__ __forceinline__ void ldsm_x2(uint32_t* r, uint32_t addr) {
    asm volatile("ldmatrix.sync.aligned.m8n8.x2.shared.b16 {%0,%1}, [%2];"
                 : "=r"(r[0]), "=r"(r[1]) : "r"(addr));
}
__device__ __forceinline__ void mma_bf16(float* c, const uint32_t* a, const uint32_t* b) {
    asm volatile(
        "mma.sync.aligned.m16n8k16.row.col.f32.bf16.bf16.f32 "
        "{%0,%1,%2,%3}, {%4,%5,%6,%7}, {%8,%9}, {%0,%1,%2,%3};"
        : "+f"(c[0]), "+f"(c[1]), "+f"(c[2]), "+f"(c[3])
        : "r"(a[0]), "r"(a[1]), "r"(a[2]), "r"(a[3]), "r"(b[0]), "r"(b[1]));
}

// 64B-row XOR swizzle: 16B-chunk index ^= (row>>1)&3. Conflict-free for
// ldmatrix 8-row groups at any chunk base (verified bank mapping).
__device__ __forceinline__ uint32_t sw_addr(uint32_t base, int row, int col_b16) {
    int chunk = (col_b16 >> 3) ^ ((row >> 1) & 3);
    return base + row * 64 + chunk * 16;
}

// ---------------- fp32 -> bf16 hi/lo split ----------------------------------
__global__ void split_kernel(const float* __restrict__ src,
                             __nv_bfloat16* __restrict__ hi,
                             __nv_bfloat16* __restrict__ lo, int n4)
{
    int i = blockIdx.x * blockDim.x + threadIdx.x;
    if (i >= n4) return;
    float4 f = ((const float4*)src)[i];
    __nv_bfloat16 h0 = __float2bfloat16(f.x), h1 = __float2bfloat16(f.y);
    __nv_bfloat16 h2 = __float2bfloat16(f.z), h3 = __float2bfloat16(f.w);
    __nv_bfloat16 l0 = __float2bfloat16(f.x - __bfloat162float(h0));
    __nv_bfloat16 l1 = __float2bfloat16(f.y - __bfloat162float(h1));
    __nv_bfloat16 l2 = __float2bfloat16(f.z - __bfloat162float(h2));
    __nv_bfloat16 l3 = __float2bfloat16(f.w - __bfloat162float(h3));
    ((__nv_bfloat162*)hi)[2*i]   = __nv_bfloat162(h0, h1);
    ((__nv_bfloat162*)hi)[2*i+1] = __nv_bfloat162(h2, h3);
    ((__nv_bfloat162*)lo)[2*i]   = __nv_bfloat162(l0, l1);
    ((__nv_bfloat162*)lo)[2*i+1] = __nv_bfloat162(l2, l3);
}

// ---------------- mma.sync split-bf16 GEMM ----------------------------------
// C[m,n] = sum_k A[m,k]*B[n,k] + bias[n], M-tile 128, N-tile 128, BK=32.
// 8 warps (2x4): warp tile 64x32. 3 passes: hi*hi + hi*lo + lo*hi.
// EPI=0: scatter into g_q/g_k/g_v; EPI=1: plain store.
#define BK 32
#define TILE_B (128 * BK * 2)          // 8192 bytes (bf16 tile)
#define STAGE_B (4 * TILE_B)           // Ahi,Alo,Bhi,Blo = 32768
#define SMEM_GEMM (2 * STAGE_B)        // 65536

template<int EPI>
__global__ void __launch_bounds__(256)
tgemm(const __nv_bfloat16* __restrict__ Ahi, const __nv_bfloat16* __restrict__ Alo,
      const __nv_bfloat16* __restrict__ Bhi, const __nv_bfloat16* __restrict__ Blo,
      const float* __restrict__ bias, float* __restrict__ Cout)
{
    extern __shared__ char smem[];
    const uint32_t sb = smem_u32(smem);

    const int tid = threadIdx.x;
    const int bm = blockIdx.y * 128;
    const int bn = blockIdx.x * 128;

    // staging role: 4 tiles x 64 threads
    const int tile = tid >> 6;           // 0=Ahi 1=Alo 2=Bhi 3=Blo
    const int slane = tid & 63;
    const __nv_bfloat16* sbase;
    if      (tile == 0) sbase = Ahi + (size_t)bm * EMBED;
    else if (tile == 1) sbase = Alo + (size_t)bm * EMBED;
    else if (tile == 2) sbase = Bhi + (size_t)bn * EMBED;
    else                sbase = Blo + (size_t)bn * EMBED;

    // warp tiling
    const int wid = tid >> 5;            // 0..7
    const int lane = tid & 31;
    const int wm = (wid >> 2) * 64;      // 0 or 64
    const int wn = (wid & 3) * 32;       // 0,32,64,96

    float acc[4][4][4];
#pragma unroll
    for (int i = 0; i < 4; i++)
#pragma unroll
        for (int j = 0; j < 4; j++)
#pragma unroll
            for (int t = 0; t < 4; t++) acc[i][j][t] = 0.f;

    const int NCHUNK = EMBED / BK;       // 32

    // issue loads for chunk c into stage s
    auto issue = [&](int c, int s) {
        const uint32_t tb = sb + s * STAGE_B + tile * TILE_B;
        const int k0 = c * BK;
#pragma unroll
        for (int t = 0; t < 8; t++) {
            const int w = slane + t * 64;       // 0..511 16B-chunks
            const int r = w >> 2;
            const int cc = w & 3;
            cp16(sw_addr(tb, r, cc * 8), sbase + (size_t)r * EMBED + k0 + cc * 8);
        }
        CP_COMMIT();
    };

    issue(0, 0);

    for (int c = 0; c < NCHUNK; c++) {
        const int s = c & 1;
        if (c + 1 < NCHUNK) { issue(c + 1, s ^ 1); CP_WAIT1(); }
        else                { CP_WAIT0(); }
        __syncthreads();

        const uint32_t sAhi = sb + s * STAGE_B;
        const uint32_t sAlo = sAhi + TILE_B;
        const uint32_t sBhi = sAhi + 2 * TILE_B;
        const uint32_t sBlo = sAhi + 3 * TILE_B;

#pragma unroll
        for (int ks = 0; ks < 2; ks++) {
            uint32_t ah[4][4], al[4][4], bh[4][2], bl[4][2];
            const int arow = wm + (lane & 15);
            const int acol = ks * 16 + (lane >> 4) * 8;
            const int brow = wn + (lane & 7);
            const int bcol = ks * 16 + ((lane >> 3) & 1) * 8;
#pragma unroll
            for (int mt = 0; mt < 4; mt++) {
                ldsm_x4(ah[mt], sw_addr(sAhi, arow + mt * 16, acol));
                ldsm_x4(al[mt], sw_addr(sAlo, arow + mt * 16, acol));
            }
#pragma unroll
            for (int nt = 0; nt < 4; nt++) {
                ldsm_x2(bh[nt], sw_addr(sBhi, brow + nt * 8, bcol));
                ldsm_x2(bl[nt], sw_addr(sBlo, brow + nt * 8, bcol));
            }
#pragma unroll
            for (int mt = 0; mt < 4; mt++)
#pragma unroll
                for (int nt = 0; nt < 4; nt++) {
                    mma_bf16(acc[mt][nt], ah[mt], bh[nt]);
                    mma_bf16(acc[mt][nt], ah[mt], bl[nt]);
                    mma_bf16(acc[mt][nt], al[mt], bh[nt]);
                }
        }
        __syncthreads();
    }

    // epilogue: frag c0,c1 -> (row = lane/4, col = (lane%4)*2), c2,c3 -> row+8
#pragma unroll
    for (int mt = 0; mt < 4; mt++) {
#pragma unroll
        for (int half = 0; half < 2; half++) {
            const int m = bm + wm + mt * 16 + (lane >> 2) + half * 8;
            const int bi = m >> 11;
            const int tt = m & 2047;
#pragma unroll
            for (int nt = 0; nt < 4; nt++) {
#pragma unroll
                for (int e = 0; e < 2; e++) {
                    const int n = bn + wn + nt * 8 + (lane & 3) * 2 + e;
                    const float val = acc[mt][nt][half * 2 + e] + bias[n];
                    if (EPI == 0) {
                        const int which = n >> 10;
                        const int cc = n & 1023;
                        const int h = cc >> 6;
                        const int d = cc & 63;
                        float* dst = (which == 0) ? g_q : (which == 1) ? g_k : g_v;
                        dst[(((size_t)(bi * NH + h)) * SEQ + tt) * DK + d] = val;
                    } else {
                        Cout[(size_t)m * EMBED + n] = val;
                    }
                }
            }
        }
    }
}

// ---------------- causal flash attention (SIMT, unchanged) -----------------
__global__ void __launch_bounds__(128) attn_kernel()
{
    const int bh = blockIdx.y;
    const int qrow = blockIdx.x * 128 + threadIdx.x;

    const float* qptr  = g_q + ((size_t)bh * SEQ + qrow) * DK;
    const float* kbase = g_k + (size_t)bh * SEQ * DK;
    const float* vbase = g_v + (size_t)bh * SEQ * DK;

    __shared__ float Ks[64 * DK];
    __shared__ float Vs[64 * DK];

    float q[DK];
#pragma unroll
    for (int i = 0; i < 16; i++) {
        float4 f = *(const float4*)(qptr + i * 4);
        q[i*4+0] = f.x; q[i*4+1] = f.y; q[i*4+2] = f.z; q[i*4+3] = f.w;
    }

    float o[DK];
#pragma unroll
    for (int d = 0; d < DK; d++) o[d] = 0.f;
    float mmax = -INFINITY, l = 0.f;
    const float scale = 0.03125f;

    const int kend = blockIdx.x * 128 + 127;

    for (int k0 = 0; k0 <= kend; k0 += 64) {
        __syncthreads();
#pragma unroll
        for (int i = 0; i < 8; i++) {
            const int idx = i * 128 + threadIdx.x;
            ((float4*)Ks)[idx] = ((const float4*)(kbase + k0 * DK))[idx];
            ((float4*)Vs)[idx] = ((const float4*)(vbase + k0 * DK))[idx];
        }
        __syncthreads();

        int jlim = qrow - k0 + 1;
        if (jlim > 64) jlim = 64;

        for (int j = 0; j < jlim; j++) {
            const float4* kr = (const float4*)(Ks + j * DK);
            float s0 = 0.f, s1 = 0.f, s2 = 0.f, s3 = 0.f;
#pragma unroll
            for (int d4 = 0; d4 < 16; d4++) {
                float4 kv = kr[d4];
                s0 = fmaf(q[d4*4+0], kv.x, s0);
                s1 = fmaf(q[d4*4+1], kv.y, s1);
                s2 = fmaf(q[d4*4+2], kv.z, s2);
                s3 = fmaf(q[d4*4+3], kv.w, s3);
            }
            float s = ((s0 + s1) + (s2 + s3)) * scale;

            if (s > mmax) {
                const float corr = __expf(mmax - s);
                l *= corr;
#pragma unroll
                for (int d = 0; d < DK; d++) o[d] *= corr;
                mmax = s;
            }
            const float p = __expf(s - mmax);
            l += p;

            const float4* vr = (const float4*)(Vs + j * DK);
#pragma unroll
            for (int d4 = 0; d4 < 16; d4++) {
                float4 vv = vr[d4];
                o[d4*4+0] = fmaf(p, vv.x, o[d4*4+0]);
                o[d4*4+1] = fmaf(p, vv.y, o[d4*4+1]);
                o[d4*4+2] = fmaf(p, vv.z, o[d4*4+2]);
                o[d4*4+3] = fmaf(p, vv.w, o[d4*4+3]);
            }
        }
    }

    const float inv = 1.0f / l;
    const int bi = bh >> 4;
    const int h = bh & 15;
    float* op = g_attn + ((size_t)(bi * SEQ + qrow)) * EMBED + h * DK;
#pragma unroll
    for (int i = 0; i < 16; i++) {
        float4 f;
        f.x = o[i*4+0]*inv; f.y = o[i*4+1]*inv; f.z = o[i*4+2]*inv; f.w = o[i*4+3]*inv;
        *(float4*)(op + i * 4) = f;
    }
}

// ---------------------------------------------------------------------------
extern "C" void kernel_launch(void* const* d_in, const int* in_sizes, int n_in,
                              void* d_out, int out_size)
{
    const float* x     = (const float*)d_in[0];
    const float* w_qkv = (const float*)d_in[1];
    const float* b_qkv = (const float*)d_in[2];
    const float* w_o   = (const float*)d_in[3];
    const float* b_o   = (const float*)d_in[4];
    float* out = (float*)d_out;

    void *xh, *xl, *qh, *ql, *oh, *ol, *ah, *al, *attn;
    cudaGetSymbolAddress(&xh, g_x_hi);   cudaGetSymbolAddress(&xl, g_x_lo);
    cudaGetSymbolAddress(&qh, g_wqkv_hi);cudaGetSymbolAddress(&ql, g_wqkv_lo);
    cudaGetSymbolAddress(&oh, g_wo_hi);  cudaGetSymbolAddress(&ol, g_wo_lo);
    cudaGetSymbolAddress(&ah, g_at_hi);  cudaGetSymbolAddress(&al, g_at_lo);
    cudaGetSymbolAddress(&attn, g_attn);

    cudaFuncSetAttribute(tgemm<0>, cudaFuncAttributeMaxDynamicSharedMemorySize, SMEM_GEMM);
    cudaFuncSetAttribute(tgemm<1>, cudaFuncAttributeMaxDynamicSharedMemorySize, SMEM_GEMM);

    // split inputs
    {
        int n4 = M_ROWS * EMBED / 4;
        split_kernel<<<(n4 + 255) / 256, 256>>>(x, (__nv_bfloat16*)xh, (__nv_bfloat16*)xl, n4);
        n4 = QKV_COLS * EMBED / 4;
        split_kernel<<<(n4 + 255) / 256, 256>>>(w_qkv, (__nv_bfloat16*)qh, (__nv_bfloat16*)ql, n4);
        n4 = EMBED * EMBED / 4;
        split_kernel<<<(n4 + 255) / 256, 256>>>(w_o, (__nv_bfloat16*)oh, (__nv_bfloat16*)ol, n4);
    }

    // QKV projection (tensor) -> g_q/g_k/g_v
    tgemm<0><<<dim3(QKV_COLS / 128, M_ROWS / 128), 256, SMEM_GEMM>>>(
        (const __nv_bfloat16*)xh, (const __nv_bfloat16*)xl,
        (const __nv_bfloat16*)qh, (const __nv_bfloat16*)ql, b_qkv, nullptr);

    // attention -> g_attn
    attn_kernel<<<dim3(SEQ / 128, BATCH * NH), 128>>>();

    // split attention output
    {
        int n4 = M_ROWS * EMBED / 4;
        split_kernel<<<(n4 + 255) / 256, 256>>>((const float*)attn,
                                                (__nv_bfloat16*)ah, (__nv_bfloat16*)al, n4);
    }

    // output projection (tensor) -> d_out
    tgemm<1><<<dim3(EMBED / 128, M_ROWS / 128), 256, SMEM_GEMM>>>(
        (const __nv_bfloat16*)ah, (const __nv_bfloat16*)al,
        (const __nv_bfloat16*)oh, (const __nv_bfloat16*)ol, b_o, out);
}

// round 5
// speedup vs baseline: 4.0300x; 2.3739x over previous
#include <cuda_runtime.h>
#include <cuda_bf16.h>
#include <math.h>
#include <stdint.h>

#define EMBED 1024
#define NH 16
#define DK 64
#define BATCH 2
#define SEQ 2048
#define M_ROWS (BATCH*SEQ)      // 4096
#define QKV_COLS (3*EMBED)      // 3072

// log2(e) / sqrt(1024) — folded into Q at the QKV epilogue
#define QSCALE 0.0450842200f

// ---------------- scratch (__device__ globals) ------------------------------
__device__ __align__(16) __nv_bfloat16 g_x_hi[M_ROWS*EMBED];
__device__ __align__(16) __nv_bfloat16 g_x_lo[M_ROWS*EMBED];
__device__ __align__(16) __nv_bfloat16 g_wqkv_hi[QKV_COLS*EMBED];
__device__ __align__(16) __nv_bfloat16 g_wqkv_lo[QKV_COLS*EMBED];
__device__ __align__(16) __nv_bfloat16 g_wo_hi[EMBED*EMBED];
__device__ __align__(16) __nv_bfloat16 g_wo_lo[EMBED*EMBED];

__device__ __align__(16) __nv_bfloat16 g_q_hi[BATCH*NH*SEQ*DK];  // [B,H,N,dk] (pre-scaled)
__device__ __align__(16) __nv_bfloat16 g_q_lo[BATCH*NH*SEQ*DK];
__device__ __align__(16) __nv_bfloat16 g_k_hi[BATCH*NH*SEQ*DK];  // [B,H,N,dk]
__device__ __align__(16) __nv_bfloat16 g_k_lo[BATCH*NH*SEQ*DK];
__device__ __align__(16) __nv_bfloat16 g_vt_hi[BATCH*NH*DK*SEQ]; // [B,H,dk,N] (transposed)
__device__ __align__(16) __nv_bfloat16 g_vt_lo[BATCH*NH*DK*SEQ];

__device__ __align__(16) __nv_bfloat16 g_at_hi[M_ROWS*EMBED];    // attention out [B,N,C]
__device__ __align__(16) __nv_bfloat16 g_at_lo[M_ROWS*EMBED];

// ---------------- PTX helpers (plain-target, sm_80-class) -------------------
__device__ __forceinline__ uint32_t smem_u32(const void* p) {
    uint32_t a;
    asm("{ .reg .u64 t; cvta.to.shared.u64 t, %1; cvt.u32.u64 %0, t; }" : "=r"(a) : "l"(p));
    return a;
}
__device__ __forceinline__ void cp16(uint32_t dst, const void* src) {
    asm volatile("cp.async.cg.shared.global [%0], [%1], 16;" :: "r"(dst), "l"(src));
}
#define CP_COMMIT() asm volatile("cp.async.commit_group;" ::: "memory")
#define CP_WAIT0()  asm volatile("cp.async.wait_group 0;" ::: "memory")
#define CP_WAIT1()  asm volatile("cp.async.wait_group 1;" ::: "memory")

__device__ __forceinline__ void ldsm_x4(uint32_t* r, uint32_t addr) {
    asm volatile("ldmatrix.sync.aligned.m8n8.x4.shared.b16 {%0,%1,%2,%3}, [%4];"
                 : "=r"(r[0]), "=r"(r[1]), "=r"(r[2]), "=r"(r[3]) : "r"(addr));
}
__device__ __forceinline__ void ldsm_x2(uint32_t* r, uint32_t addr) {
    asm volatile("ldmatrix.sync.aligned.m8n8.x2.shared.b16 {%0,%1}, [%2];"
                 : "=r"(r[0]), "=r"(r[1]) : "r"(addr));
}
__device__ __forceinline__ void mma_bf16(float* c, const uint32_t* a, const uint32_t* b) {
    asm volatile(
        "mma.sync.aligned.m16n8k16.row.col.f32.bf16.bf16.f32 "
        "{%0,%1,%2,%3}, {%4,%5,%6,%7}, {%8,%9}, {%0,%1,%2,%3};"
        : "+f"(c[0]), "+f"(c[1]), "+f"(c[2]), "+f"(c[3])
        : "r"(a[0]), "r"(a[1]), "r"(a[2]), "r"(a[3]), "r"(b[0]), "r"(b[1]));
}
__device__ __forceinline__ float ex2(float x) {
    float y; asm("ex2.approx.f32 %0, %1;" : "=f"(y) : "f"(x)); return y;
}

// 64B-row XOR swizzle (GEMM tiles, BK=32 -> 64B rows)
__device__ __forceinline__ uint32_t sw_addr(uint32_t base, int row, int col_b16) {
    int chunk = (col_b16 >> 3) ^ ((row >> 1) & 3);
    return base + row * 64 + chunk * 16;
}
// 128B-row XOR swizzle (attention tiles, 64 bf16 = 128B rows). chunk in 16B units.
__device__ __forceinline__ uint32_t swza(uint32_t base, int row, int chunk) {
    return base + row * 128 + ((chunk ^ (row & 7)) * 16);
}

// ---------------- fp32 -> bf16 hi/lo split ----------------------------------
__global__ void split_kernel(const float* __restrict__ src,
                             __nv_bfloat16* __restrict__ hi,
                             __nv_bfloat16* __restrict__ lo, int n4)
{
    int i = blockIdx.x * blockDim.x + threadIdx.x;
    if (i >= n4) return;
    float4 f = ((const float4*)src)[i];
    __nv_bfloat16 h0 = __float2bfloat16(f.x), h1 = __float2bfloat16(f.y);
    __nv_bfloat16 h2 = __float2bfloat16(f.z), h3 = __float2bfloat16(f.w);
    __nv_bfloat16 l0 = __float2bfloat16(f.x - __bfloat162float(h0));
    __nv_bfloat16 l1 = __float2bfloat16(f.y - __bfloat162float(h1));
    __nv_bfloat16 l2 = __float2bfloat16(f.z - __bfloat162float(h2));
    __nv_bfloat16 l3 = __float2bfloat16(f.w - __bfloat162float(h3));
    ((__nv_bfloat162*)hi)[2*i]   = __nv_bfloat162(h0, h1);
    ((__nv_bfloat162*)hi)[2*i+1] = __nv_bfloat162(h2, h3);
    ((__nv_bfloat162*)lo)[2*i]   = __nv_bfloat162(l0, l1);
    ((__nv_bfloat162*)lo)[2*i+1] = __nv_bfloat162(l2, l3);
}

// ---------------- mma.sync split-bf16 GEMM ----------------------------------
// EPI=0: QKV -> q/k (bf16 hi/lo, [B,H,N,dk], q pre-scaled) + v^T ([B,H,dk,N])
// EPI=1: out-proj -> fp32 Cout
#define BK 32
#define TILE_B (128 * BK * 2)          // 8192 bytes
#define STAGE_B (4 * TILE_B)           // 32768
#define SMEM_GEMM (2 * STAGE_B)        // 65536

template<int EPI>
__global__ void __launch_bounds__(256)
tgemm(const __nv_bfloat16* __restrict__ Ahi, const __nv_bfloat16* __restrict__ Alo,
      const __nv_bfloat16* __restrict__ Bhi, const __nv_bfloat16* __restrict__ Blo,
      const float* __restrict__ bias, float* __restrict__ Cout)
{
    extern __shared__ char smem[];
    const uint32_t sb = smem_u32(smem);

    const int tid = threadIdx.x;
    const int bm = blockIdx.y * 128;
    const int bn = blockIdx.x * 128;

    const int tile = tid >> 6;
    const int slane = tid & 63;
    const __nv_bfloat16* sbase;
    if      (tile == 0) sbase = Ahi + (size_t)bm * EMBED;
    else if (tile == 1) sbase = Alo + (size_t)bm * EMBED;
    else if (tile == 2) sbase = Bhi + (size_t)bn * EMBED;
    else                sbase = Blo + (size_t)bn * EMBED;

    const int wid = tid >> 5;
    const int lane = tid & 31;
    const int wm = (wid >> 2) * 64;
    const int wn = (wid & 3) * 32;

    float acc[4][4][4];
#pragma unroll
    for (int i = 0; i < 4; i++)
#pragma unroll
        for (int j = 0; j < 4; j++)
#pragma unroll
            for (int t = 0; t < 4; t++) acc[i][j][t] = 0.f;

    const int NCHUNK = EMBED / BK;

    auto issue = [&](int c, int s) {
        const uint32_t tb = sb + s * STAGE_B + tile * TILE_B;
        const int k0 = c * BK;
#pragma unroll
        for (int t = 0; t < 8; t++) {
            const int w = slane + t * 64;
            const int r = w >> 2;
            const int cc = w & 3;
            cp16(sw_addr(tb, r, cc * 8), sbase + (size_t)r * EMBED + k0 + cc * 8);
        }
        CP_COMMIT();
    };

    issue(0, 0);

    for (int c = 0; c < NCHUNK; c++) {
        const int s = c & 1;
        if (c + 1 < NCHUNK) { issue(c + 1, s ^ 1); CP_WAIT1(); }
        else                { CP_WAIT0(); }
        __syncthreads();

        const uint32_t sAhi = sb + s * STAGE_B;
        const uint32_t sAlo = sAhi + TILE_B;
        const uint32_t sBhi = sAhi + 2 * TILE_B;
        const uint32_t sBlo = sAhi + 3 * TILE_B;

#pragma unroll
        for (int ks = 0; ks < 2; ks++) {
            uint32_t ah[4][4], al[4][4], bh[4][2], bl[4][2];
            const int arow = wm + (lane & 15);
            const int acol = ks * 16 + (lane >> 4) * 8;
            const int brow = wn + (lane & 7);
            const int bcol = ks * 16 + ((lane >> 3) & 1) * 8;
#pragma unroll
            for (int mt = 0; mt < 4; mt++) {
                ldsm_x4(ah[mt], sw_addr(sAhi, arow + mt * 16, acol));
                ldsm_x4(al[mt], sw_addr(sAlo, arow + mt * 16, acol));
            }
#pragma unroll
            for (int nt = 0; nt < 4; nt++) {
                ldsm_x2(bh[nt], sw_addr(sBhi, brow + nt * 8, bcol));
                ldsm_x2(bl[nt], sw_addr(sBlo, brow + nt * 8, bcol));
            }
#pragma unroll
            for (int mt = 0; mt < 4; mt++)
#pragma unroll
                for (int nt = 0; nt < 4; nt++) {
                    mma_bf16(acc[mt][nt], ah[mt], bh[nt]);
                    mma_bf16(acc[mt][nt], ah[mt], bl[nt]);
                    mma_bf16(acc[mt][nt], al[mt], bh[nt]);
                }
        }
        __syncthreads();
    }

#pragma unroll
    for (int mt = 0; mt < 4; mt++) {
#pragma unroll
        for (int half = 0; half < 2; half++) {
            const int m = bm + wm + mt * 16 + (lane >> 2) + half * 8;
            const int bi = m >> 11;
            const int tt = m & 2047;
#pragma unroll
            for (int nt = 0; nt < 4; nt++) {
                const int n0 = bn + wn + nt * 8 + (lane & 3) * 2;
                float v0 = acc[mt][nt][half * 2 + 0] + bias[n0];
                float v1 = acc[mt][nt][half * 2 + 1] + bias[n0 + 1];
                if (EPI == 0) {
                    const int which = n0 >> 10;
                    const int cc = n0 & 1023;
                    const int h = cc >> 6;
                    const int d = cc & 63;
                    const int bh = bi * NH + h;
                    if (which == 0) { v0 *= QSCALE; v1 *= QSCALE; }
                    __nv_bfloat16 h0 = __float2bfloat16(v0);
                    __nv_bfloat16 h1 = __float2bfloat16(v1);
                    __nv_bfloat16 l0 = __float2bfloat16(v0 - __bfloat162float(h0));
                    __nv_bfloat16 l1 = __float2bfloat16(v1 - __bfloat162float(h1));
                    if (which < 2) {
                        __nv_bfloat16* dhi = which ? g_k_hi : g_q_hi;
                        __nv_bfloat16* dlo = which ? g_k_lo : g_q_lo;
                        const size_t idx = ((size_t)bh * SEQ + tt) * DK + d;
                        *(__nv_bfloat162*)(dhi + idx) = __nv_bfloat162(h0, h1);
                        *(__nv_bfloat162*)(dlo + idx) = __nv_bfloat162(l0, l1);
                    } else {
                        const size_t idx = ((size_t)bh * DK + d) * SEQ + tt;
                        g_vt_hi[idx] = h0; g_vt_hi[idx + SEQ] = h1;
                        g_vt_lo[idx] = l0; g_vt_lo[idx + SEQ] = l1;
                    }
                } else {
                    Cout[(size_t)m * EMBED + n0]     = v0;
                    Cout[(size_t)m * EMBED + n0 + 1] = v1;
                }
            }
        }
    }
}

// ---------------- tensor-core causal flash attention ------------------------
// CTA: 64 queries (4 warps x 16 rows), key tiles of 64.
// smem: Qhi(8K) Qlo(8K) + 2 stages x {Khi,Klo,VThi,VTlo} (8K each) = 80K
#define ATT_SMEM (16384 + 2 * 32768)

__global__ void __launch_bounds__(128) attn_mma()
{
    extern __shared__ char smem[];
    const uint32_t sb = smem_u32(smem);
    const uint32_t qhi_s = sb, qlo_s = sb + 8192;
    const uint32_t stage0 = sb + 16384;

    const int tid = threadIdx.x;
    const int lane = tid & 31;
    const int wid = tid >> 5;
    const int g = lane >> 2;           // row in group
    const int tg = lane & 3;           // thread in group
    const int bh = blockIdx.y;         // b*16+h
    const int qb = blockIdx.x;         // 64-row query block

    const __nv_bfloat16* qhi_g = g_q_hi + ((size_t)bh * SEQ + qb * 64) * DK;
    const __nv_bfloat16* qlo_g = g_q_lo + ((size_t)bh * SEQ + qb * 64) * DK;
    const __nv_bfloat16* khi_g = g_k_hi + (size_t)bh * SEQ * DK;
    const __nv_bfloat16* klo_g = g_k_lo + (size_t)bh * SEQ * DK;
    const __nv_bfloat16* vthi_g = g_vt_hi + (size_t)bh * DK * SEQ;
    const __nv_bfloat16* vtlo_g = g_vt_lo + (size_t)bh * DK * SEQ;

    // stage Q (hi+lo): 64 rows x 128B each
#pragma unroll
    for (int i = 0; i < 4; i++) {
        const int w = tid + i * 128;       // 0..511
        const int r = w >> 3, c = w & 7;
        cp16(swza(qhi_s, r, c), qhi_g + (size_t)r * DK + c * 8);
        cp16(swza(qlo_s, r, c), qlo_g + (size_t)r * DK + c * 8);
    }
    CP_COMMIT();

    auto issue_tile = [&](int kt, int s) {
        const uint32_t st = stage0 + s * 32768;
        const int k0 = kt * 64;
#pragma unroll
        for (int i = 0; i < 4; i++) {
            const int w = tid + i * 128;
            const int r = w >> 3, c = w & 7;
            const uint32_t off = r * 128 + ((c ^ (r & 7)) * 16);
            cp16(st + off,         khi_g + (size_t)(k0 + r) * DK + c * 8);
            cp16(st + 8192 + off,  klo_g + (size_t)(k0 + r) * DK + c * 8);
            cp16(st + 16384 + off, vthi_g + (size_t)r * SEQ + k0 + c * 8);
            cp16(st + 24576 + off, vtlo_g + (size_t)r * SEQ + k0 + c * 8);
        }
        CP_COMMIT();
    };

    issue_tile(0, 0);

    uint32_t qh[4][4], ql[4][4];
    float oacc[8][4];
#pragma unroll
    for (int nt = 0; nt < 8; nt++)
#pragma unroll
        for (int t = 0; t < 4; t++) oacc[nt][t] = 0.f;
    float m0 = -1e30f, m1 = -1e30f, l0 = 0.f, l1 = 0.f;

    for (int kt = 0; kt <= qb; kt++) {
        const int s = kt & 1;
        if (kt < qb) { issue_tile(kt + 1, s ^ 1); CP_WAIT1(); }
        else         { CP_WAIT0(); }
        __syncthreads();

        if (kt == 0) {
            const int arow = wid * 16 + (lane & 15);
            const int ach = lane >> 4;       // chunk sub-offset
#pragma unroll
            for (int kc = 0; kc < 4; kc++) {
                ldsm_x4(qh[kc], swza(qhi_s, arow, kc * 2 + ach));
                ldsm_x4(ql[kc], swza(qlo_s, arow, kc * 2 + ach));
            }
        }

        const uint32_t sK  = stage0 + s * 32768;
        const uint32_t sKl = sK + 8192;
        const uint32_t sVT = sK + 16384;
        const uint32_t sVTl = sK + 24576;

        // ---- S = Q K^T (log2-domain, scale pre-folded into Q) ----
        float sacc[8][4];
#pragma unroll
        for (int nt = 0; nt < 8; nt++)
#pragma unroll
            for (int t = 0; t < 4; t++) sacc[nt][t] = 0.f;

        const int br = lane & 7;
        const int bc = (lane >> 3) & 1;
#pragma unroll
        for (int kc = 0; kc < 4; kc++) {
            uint32_t bhf[8][2], blf[8][2];
#pragma unroll
            for (int nt = 0; nt < 8; nt++) {
                ldsm_x2(bhf[nt], swza(sK,  nt * 8 + br, kc * 2 + bc));
                ldsm_x2(blf[nt], swza(sKl, nt * 8 + br, kc * 2 + bc));
            }
#pragma unroll
            for (int nt = 0; nt < 8; nt++) {
                mma_bf16(sacc[nt], qh[kc], bhf[nt]);
                mma_bf16(sacc[nt], qh[kc], blf[nt]);
                mma_bf16(sacc[nt], ql[kc], bhf[nt]);
            }
        }

        // ---- causal mask (diagonal tile only) ----
        if (kt == qb) {
#pragma unroll
            for (int nt = 0; nt < 8; nt++)
#pragma unroll
                for (int idx = 0; idx < 4; idx++) {
                    const int key = nt * 8 + tg * 2 + (idx & 1);
                    const int qr  = wid * 16 + g + (idx >> 1) * 8;
                    if (key > qr) sacc[nt][idx] = -1e30f;
                }
        }

        // ---- online softmax (log2 domain) ----
        float mx0 = -1e30f, mx1 = -1e30f;
#pragma unroll
        for (int nt = 0; nt < 8; nt++) {
            mx0 = fmaxf(mx0, fmaxf(sacc[nt][0], sacc[nt][1]));
            mx1 = fmaxf(mx1, fmaxf(sacc[nt][2], sacc[nt][3]));
        }
        mx0 = fmaxf(mx0, __shfl_xor_sync(0xffffffffu, mx0, 1));
        mx0 = fmaxf(mx0, __shfl_xor_sync(0xffffffffu, mx0, 2));
        mx1 = fmaxf(mx1, __shfl_xor_sync(0xffffffffu, mx1, 1));
        mx1 = fmaxf(mx1, __shfl_xor_sync(0xffffffffu, mx1, 2));

        const float mn0 = fmaxf(m0, mx0);
        const float mn1 = fmaxf(m1, mx1);
        const float a0 = ex2(m0 - mn0);
        const float a1 = ex2(m1 - mn1);
        m0 = mn0; m1 = mn1;
        l0 *= a0; l1 *= a1;
#pragma unroll
        for (int nt = 0; nt < 8; nt++) {
            oacc[nt][0] *= a0; oacc[nt][1] *= a0;
            oacc[nt][2] *= a1; oacc[nt][3] *= a1;
        }

        uint32_t ph[4][4], pl[4][4];
        float ps0 = 0.f, ps1 = 0.f;
#pragma unroll
        for (int nt = 0; nt < 8; nt++) {
            const float p0 = ex2(sacc[nt][0] - mn0);
            const float p1 = ex2(sacc[nt][1] - mn0);
            const float p2 = ex2(sacc[nt][2] - mn1);
            const float p3 = ex2(sacc[nt][3] - mn1);
            ps0 += p0 + p1; ps1 += p2 + p3;
            const int kc = nt >> 1;
            const int r = (nt & 1) * 2;          // regs 0,1 or 2,3 (k or k+8)
            __nv_bfloat162 hp01 = __floats2bfloat162_rn(p0, p1);
            __nv_bfloat162 hp23 = __floats2bfloat162_rn(p2, p3);
            __nv_bfloat162 lp01 = __floats2bfloat162_rn(
                p0 - __bfloat162float(hp01.x), p1 - __bfloat162float(hp01.y));
            __nv_bfloat162 lp23 = __floats2bfloat162_rn(
                p2 - __bfloat162float(hp23.x), p3 - __bfloat162float(hp23.y));
            ph[kc][r + 0] = *(uint32_t*)&hp01;   // A-frag a0/a2: row g
            ph[kc][r + 1] = *(uint32_t*)&hp23;   // A-frag a1/a3: row g+8
            pl[kc][r + 0] = *(uint32_t*)&lp01;
            pl[kc][r + 1] = *(uint32_t*)&lp23;
        }
        // FIX (round-4 NaN): l is a ROW sum — reduce partial sums across the
        // 4-thread quad. Without this, fully-masked threads kept l=0 -> 1/l=inf
        // -> 0*inf = NaN, and all rows were normalized by partial sums.
        ps0 += __shfl_xor_sync(0xffffffffu, ps0, 1);
        ps0 += __shfl_xor_sync(0xffffffffu, ps0, 2);
        ps1 += __shfl_xor_sync(0xffffffffu, ps1, 1);
        ps1 += __shfl_xor_sync(0xffffffffu, ps1, 2);
        l0 += ps0; l1 += ps1;

        // ---- O += P V ----
#pragma unroll
        for (int kc = 0; kc < 4; kc++) {
            uint32_t vh[8][2], vl[8][2];
#pragma unroll
            for (int nt = 0; nt < 8; nt++) {
                ldsm_x2(vh[nt], swza(sVT,  nt * 8 + br, kc * 2 + bc));
                ldsm_x2(vl[nt], swza(sVTl, nt * 8 + br, kc * 2 + bc));
            }
#pragma unroll
            for (int nt = 0; nt < 8; nt++) {
                mma_bf16(oacc[nt], ph[kc], vh[nt]);
                mma_bf16(oacc[nt], ph[kc], vl[nt]);
                mma_bf16(oacc[nt], pl[kc], vh[nt]);
            }
        }
        __syncthreads();   // protect stage before re-staging
    }

    // ---- normalize + write bf16 hi/lo [B,N,C] ----
    const float inv0 = 1.0f / l0;
    const float inv1 = 1.0f / l1;
    const int bi = bh >> 4;
    const int h  = bh & 15;
    const int row0 = bi * SEQ + qb * 64 + wid * 16 + g;
#pragma unroll
    for (int nt = 0; nt < 8; nt++) {
        const int col = h * 64 + nt * 8 + tg * 2;
        {
            const float v0 = oacc[nt][0] * inv0, v1 = oacc[nt][1] * inv0;
            __nv_bfloat162 hp = __floats2bfloat162_rn(v0, v1);
            __nv_bfloat162 lp = __floats2bfloat162_rn(
                v0 - __bfloat162float(hp.x), v1 - __bfloat162float(hp.y));
            *(__nv_bfloat162*)(g_at_hi + (size_t)row0 * EMBED + col) = hp;
            *(__nv_bfloat162*)(g_at_lo + (size_t)row0 * EMBED + col) = lp;
        }
        {
            const float v0 = oacc[nt][2] * inv1, v1 = oacc[nt][3] * inv1;
            __nv_bfloat162 hp = __floats2bfloat162_rn(v0, v1);
            __nv_bfloat162 lp = __floats2bfloat162_rn(
                v0 - __bfloat162float(hp.x), v1 - __bfloat162float(hp.y));
            *(__nv_bfloat162*)(g_at_hi + (size_t)(row0 + 8) * EMBED + col) = hp;
            *(__nv_bfloat162*)(g_at_lo + (size_t)(row0 + 8) * EMBED + col) = lp;
        }
    }
}

// ---------------------------------------------------------------------------
extern "C" void kernel_launch(void* const* d_in, const int* in_sizes, int n_in,
                              void* d_out, int out_size)
{
    const float* x     = (const float*)d_in[0];
    const float* w_qkv = (const float*)d_in[1];
    const float* b_qkv = (const float*)d_in[2];
    const float* w_o   = (const float*)d_in[3];
    const float* b_o   = (const float*)d_in[4];
    float* out = (float*)d_out;

    void *xh, *xl, *qh, *ql, *oh, *ol, *ah, *al;
    cudaGetSymbolAddress(&xh, g_x_hi);    cudaGetSymbolAddress(&xl, g_x_lo);
    cudaGetSymbolAddress(&qh, g_wqkv_hi); cudaGetSymbolAddress(&ql, g_wqkv_lo);
    cudaGetSymbolAddress(&oh, g_wo_hi);   cudaGetSymbolAddress(&ol, g_wo_lo);
    cudaGetSymbolAddress(&ah, g_at_hi);   cudaGetSymbolAddress(&al, g_at_lo);

    cudaFuncSetAttribute(tgemm<0>, cudaFuncAttributeMaxDynamicSharedMemorySize, SMEM_GEMM);
    cudaFuncSetAttribute(tgemm<1>, cudaFuncAttributeMaxDynamicSharedMemorySize, SMEM_GEMM);
    cudaFuncSetAttribute(attn_mma, cudaFuncAttributeMaxDynamicSharedMemorySize, ATT_SMEM);

    // split inputs to bf16 hi/lo
    {
        int n4 = M_ROWS * EMBED / 4;
        split_kernel<<<(n4 + 255) / 256, 256>>>(x, (__nv_bfloat16*)xh, (__nv_bfloat16*)xl, n4);
        n4 = QKV_COLS * EMBED / 4;
        split_kernel<<<(n4 + 255) / 256, 256>>>(w_qkv, (__nv_bfloat16*)qh, (__nv_bfloat16*)ql, n4);
        n4 = EMBED * EMBED / 4;
        split_kernel<<<(n4 + 255) / 256, 256>>>(w_o, (__nv_bfloat16*)oh, (__nv_bfloat16*)ol, n4);
    }

    // QKV projection -> q/k hi/lo + v^T hi/lo
    tgemm<0><<<dim3(QKV_COLS / 128, M_ROWS / 128), 256, SMEM_GEMM>>>(
        (const __nv_bfloat16*)xh, (const __nv_bfloat16*)xl,
        (const __nv_bfloat16*)qh, (const __nv_bfloat16*)ql, b_qkv, nullptr);

    // tensor-core flash attention -> g_at hi/lo
    attn_mma<<<dim3(SEQ / 64, BATCH * NH), 128, ATT_SMEM>>>();

    // output projection -> d_out
    tgemm<1><<<dim3(EMBED / 128, M_ROWS / 128), 256, SMEM_GEMM>>>(
        (const __nv_bfloat16*)ah, (const __nv_bfloat16*)al,
        (const __nv_bfloat16*)oh, (const __nv_bfloat16*)ol, b_o, out);
}